// round 5
// baseline (speedup 1.0000x reference)
#include <cuda_runtime.h>
#include <cuda_bf16.h>

// Sparse generative transpose conv (3x3x3, stride 2), pruned to guide coords.
// R5: offset-grouped gather-GEMM. Probe builds 27 per-offset (guide,input) pair
// buckets; GEMM amortizes W[o] (smem) across 128-row tiles; epilogue scatters
// with atomicAdd (rare conflicts). Probe also writes bias/zero rows (out init).

#define FULLMASK 0xffffffffu
#define CAP 400000           // max pairs per offset (<= Ng)
#define TILE 128

__device__ int    g_grid[1 << 21];        // 128^3 cells -> input index or -1
__device__ float4 g_Wq[27 * 512];         // Wq[o][k4][j] = W[o][4k4+0..3][j]
__device__ int    g_is64;                 // 1 if coords are int64
__device__ int    g_cnt[27];              // pairs per offset
__device__ int2   g_pairs[27 * CAP];      // (guide, input) pairs per offset
__device__ int    g_nwork;                // number of GEMM tiles
__device__ int    g_work[27 * ((CAP + TILE - 1) / TILE) + 32];

__device__ __forceinline__ unsigned long long pack2(float a, float b) {
    unsigned long long r;
    asm("mov.b64 %0, {%1, %2};" : "=l"(r) : "f"(a), "f"(b));
    return r;
}
__device__ __forceinline__ void unpack2(unsigned long long v, float& a, float& b) {
    asm("mov.b64 {%0, %1}, %2;" : "=f"(a), "=f"(b) : "l"(v));
}
__device__ __forceinline__ void fma2(unsigned long long& acc,
                                     unsigned long long a, unsigned long long b) {
    asm("fma.rn.f32x2 %0, %1, %2, %0;" : "+l"(acc) : "l"(a), "l"(b));
}

// int64 layout: odd int32 words are sign-extension halves of coords >= -1 -> {0,-1}.
__global__ void detect_dtype(const int* __restrict__ gc) {
    int bad = 0;
    for (int i = 1; i < 2048; i += 2) {
        int v = gc[i];
        bad |= (v != 0) & (v != -1);
    }
    g_is64 = bad ? 0 : 1;
}

__device__ __forceinline__ void load_xyz(const void* p, long long row,
                                         int& x, int& y, int& z) {
    if (g_is64) {
        const long long* q = (const long long*)p + row * 4;
        x = (int)q[1]; y = (int)q[2]; z = (int)q[3];
    } else {
        const int* q = (const int*)p + row * 4;
        x = q[1]; y = q[2]; z = q[3];
    }
}

__global__ void populate_grid(const void* __restrict__ ic, int np) {
    int i = blockIdx.x * blockDim.x + threadIdx.x;
    if (i >= np) return;
    int x, y, z;
    load_xyz(ic, i, x, y, z);
    if (((unsigned)x < 256u) & ((unsigned)y < 256u) & ((unsigned)z < 256u) &
        (((x | y | z) & 1) == 0)) {
        int cell = (x >> 1) | ((y >> 1) << 7) | ((z >> 1) << 14);
        g_grid[cell] = i;
    }
}

__global__ void pack_weights(const float* __restrict__ W) {
    int t = blockIdx.x * blockDim.x + threadIdx.x;
    if (t >= 27 * 512) return;
    int j  = t & 31;
    int k4 = (t >> 5) & 15;
    int o  = t >> 9;
    const float* b = W + ((o * 64 + 4 * k4) * 32 + j);
    g_Wq[t] = make_float4(b[0], b[32], b[64], b[96]);
}

// Thread-per-guide: probe 27 taps (parity-pruned), append pairs, init out row.
__global__ __launch_bounds__(256) void probe_kernel(
    const void*  __restrict__ guide,
    const float* __restrict__ bias,
    float*       __restrict__ out,
    int ng)
{
    int g = blockIdx.x * blockDim.x + threadIdx.x;
    if (g >= ng) return;
    int qx, qy, qz;
    load_xyz(guide, g, qx, qy, qz);

    bool any = false;
    #pragma unroll
    for (int o = 0; o < 27; o++) {
        const int ox = o / 9 - 1, oy = (o / 3) % 3 - 1, oz = o % 3 - 1;
        int px = qx - ox, py = qy - oy, pz = qz - oz;
        if ((((px | py | pz) & 1) == 0) &
            ((unsigned)px < 256u) & ((unsigned)py < 256u) & ((unsigned)pz < 256u)) {
            int cell = (px >> 1) | ((py >> 1) << 7) | ((pz >> 1) << 14);
            int idx = g_grid[cell];
            if (idx >= 0) {
                int pos = atomicAdd(&g_cnt[o], 1);
                g_pairs[o * CAP + pos] = make_int2(g, idx);
                any = true;
            }
        }
    }
    // Initialize output row: bias (hits follow via atomicAdd) or exact zero.
    float4* orow = (float4*)(out + (long long)g * 32);
    if (any) {
        const float4* b4 = (const float4*)bias;
        #pragma unroll
        for (int i = 0; i < 8; i++) orow[i] = b4[i];
    } else {
        float4 zf = make_float4(0.f, 0.f, 0.f, 0.f);
        #pragma unroll
        for (int i = 0; i < 8; i++) orow[i] = zf;
    }
}

// One block: build compact (offset, tile) worklist.
__global__ void build_work() {
    __shared__ int tl[27];
    __shared__ int base[28];
    int t = threadIdx.x;
    if (t < 27) tl[t] = (g_cnt[t] + TILE - 1) / TILE;
    __syncthreads();
    if (t == 0) {
        int s = 0;
        for (int i = 0; i < 27; i++) { base[i] = s; s += tl[i]; }
        g_nwork = s;
    }
    __syncthreads();
    if (t < 27) {
        int b = base[t], n = tl[t];
        for (int i = 0; i < n; i++) g_work[b + i] = (t << 16) | i;
    }
}

// CTA = one (offset, 128-row) tile. W[o] in smem, warp computes 16 rows x 32 cols.
__global__ __launch_bounds__(256) void gemm_kernel(
    const float* __restrict__ feats,
    float*       __restrict__ out)
{
    __shared__ int2   pairs[TILE];
    __shared__ float4 Wsh[512];          // 8 KB: W[o] packed by k4
    __shared__ float4 Fsh[TILE * 16];    // 32 KB: features [row][k4]

    int t = threadIdx.x, lane = t & 31, w = t >> 5;
    int nwork = g_nwork;

    for (int widx = blockIdx.x; widx < nwork; widx += gridDim.x) {
        int wk = g_work[widx];
        int o = wk >> 16, tile = wk & 0xffff;
        int cnt = g_cnt[o];
        int m0 = tile << 7;
        int m = min(TILE, cnt - m0);

        if (t < TILE && t < m) pairs[t] = g_pairs[o * CAP + m0 + t];
        Wsh[t]       = g_Wq[o * 512 + t];
        Wsh[t + 256] = g_Wq[o * 512 + t + 256];
        __syncthreads();

        const float4* f4p = (const float4*)feats;
        for (int v = t; v < (m << 4); v += 256) {
            int row = v >> 4, k4 = v & 15;
            Fsh[v] = f4p[(long long)pairs[row].y * 16 + k4];
        }
        __syncthreads();

        int r0 = w << 4;
        unsigned long long acc[16];
        #pragma unroll
        for (int r = 0; r < 16; r++) acc[r] = 0ull;

        #pragma unroll
        for (int k4 = 0; k4 < 16; k4++) {
            float4 w4 = Wsh[k4 * 32 + lane];                 // conflict-free LDS.128
            unsigned long long wxy = pack2(w4.x, w4.y);
            unsigned long long wzw = pack2(w4.z, w4.w);
            #pragma unroll
            for (int r = 0; r < 16; r++) {
                float4 f4 = Fsh[((r0 + r) << 4) + k4];       // broadcast LDS.128
                fma2(acc[r], pack2(f4.x, f4.y), wxy);
                fma2(acc[r], pack2(f4.z, f4.w), wzw);
            }
        }

        #pragma unroll
        for (int r = 0; r < 16; r++) {
            if (r0 + r < m) {
                float a, b;
                unpack2(acc[r], a, b);
                atomicAdd(&out[(long long)pairs[r0 + r].x * 32 + lane], a + b);
            }
        }
        __syncthreads();
    }
}

extern "C" void kernel_launch(void* const* d_in, const int* in_sizes, int n_in,
                              void* d_out, int out_size) {
    // Identify inputs by element count (order-agnostic).
    const float* feats = nullptr;
    const float* W     = nullptr;
    const float* bias  = nullptr;
    const void*  ic    = nullptr;
    const void*  gc    = nullptr;
    int np = 200000, ng = 400000;
    for (int i = 0; i < n_in; i++) {
        switch (in_sizes[i]) {
            case 12800000: feats = (const float*)d_in[i]; break;            // [Np,64]
            case 55296:    W     = (const float*)d_in[i]; break;            // [27,64,32]
            case 32:       bias  = (const float*)d_in[i]; break;            // [32]
            case 800000:   ic    = d_in[i]; np = in_sizes[i] / 4; break;    // [Np,4]
            case 1600000:  gc    = d_in[i]; ng = in_sizes[i] / 4; break;    // [Ng,4]
            default: break;
        }
    }
    if (!feats) feats = (const float*)d_in[0];
    if (!W)     W     = (const float*)d_in[1];
    if (!bias)  bias  = (const float*)d_in[2];
    if (!ic)    ic    = d_in[3];
    if (!gc)    gc    = d_in[4];
    float* out = (float*)d_out;

    void* gptr = nullptr;
    cudaGetSymbolAddress(&gptr, g_grid);
    cudaMemsetAsync(gptr, 0xFF, sizeof(int) * (1 << 21), 0);
    void* cptr = nullptr;
    cudaGetSymbolAddress(&cptr, g_cnt);
    cudaMemsetAsync(cptr, 0, sizeof(int) * 27, 0);

    detect_dtype<<<1, 1>>>((const int*)gc);
    populate_grid<<<(np + 255) / 256, 256>>>(ic, np);
    pack_weights<<<(27 * 512 + 255) / 256, 256>>>(W);
    probe_kernel<<<(ng + 255) / 256, 256>>>(gc, bias, out, ng);
    build_work<<<1, 32>>>();
    gemm_kernel<<<2048, 256>>>(feats, out);
}

// round 6
// speedup vs baseline: 1.6726x; 1.6726x over previous
#include <cuda_runtime.h>
#include <cuda_bf16.h>

// Sparse generative transpose conv (3x3x3, stride 2), pruned to guide coords.
// R6: offset-grouped gather-GEMM with block-aggregated bucket counters
// (fixes R5's 27-counter global-atomic serialization wall in the probe).

#define FULLMASK 0xffffffffu
#define CAP 400000           // max pairs per offset (<= Ng)
#define TILE 128

__device__ int    g_grid[1 << 21];        // 128^3 cells -> input index or -1
__device__ float4 g_Wq[27 * 512];         // Wq[o][k4][j] = W[o][4k4+0..3][j]
__device__ int    g_is64;                 // 1 if coords are int64
__device__ int    g_cnt[27];              // pairs per offset
__device__ int2   g_pairs[27 * CAP];      // (guide, input) pairs per offset
__device__ int    g_nwork;                // number of GEMM tiles
__device__ int    g_work[27 * ((CAP + TILE - 1) / TILE) + 32];

__device__ __forceinline__ unsigned long long pack2(float a, float b) {
    unsigned long long r;
    asm("mov.b64 %0, {%1, %2};" : "=l"(r) : "f"(a), "f"(b));
    return r;
}
__device__ __forceinline__ void unpack2(unsigned long long v, float& a, float& b) {
    asm("mov.b64 {%0, %1}, %2;" : "=f"(a), "=f"(b) : "l"(v));
}
__device__ __forceinline__ void fma2(unsigned long long& acc,
                                     unsigned long long a, unsigned long long b) {
    asm("fma.rn.f32x2 %0, %1, %2, %0;" : "+l"(acc) : "l"(a), "l"(b));
}

// int64 layout: odd int32 words are sign-extension halves of coords >= -1 -> {0,-1}.
__global__ void detect_dtype(const int* __restrict__ gc) {
    int bad = 0;
    for (int i = 1; i < 2048; i += 2) {
        int v = gc[i];
        bad |= (v != 0) & (v != -1);
    }
    g_is64 = bad ? 0 : 1;
}

__device__ __forceinline__ void load_xyz(const void* p, long long row,
                                         int& x, int& y, int& z) {
    if (g_is64) {
        const long long* q = (const long long*)p + row * 4;
        x = (int)q[1]; y = (int)q[2]; z = (int)q[3];
    } else {
        const int* q = (const int*)p + row * 4;
        x = q[1]; y = q[2]; z = q[3];
    }
}

__global__ void populate_grid(const void* __restrict__ ic, int np) {
    int i = blockIdx.x * blockDim.x + threadIdx.x;
    if (i >= np) return;
    int x, y, z;
    load_xyz(ic, i, x, y, z);
    if (((unsigned)x < 256u) & ((unsigned)y < 256u) & ((unsigned)z < 256u) &
        (((x | y | z) & 1) == 0)) {
        int cell = (x >> 1) | ((y >> 1) << 7) | ((z >> 1) << 14);
        g_grid[cell] = i;
    }
}

__global__ void pack_weights(const float* __restrict__ W) {
    int t = blockIdx.x * blockDim.x + threadIdx.x;
    if (t >= 27 * 512) return;
    int j  = t & 31;
    int k4 = (t >> 5) & 15;
    int o  = t >> 9;
    const float* b = W + ((o * 64 + 4 * k4) * 32 + j);
    g_Wq[t] = make_float4(b[0], b[32], b[64], b[96]);
}

// Thread-per-guide probe with BLOCK-aggregated bucket counters:
// smem counts per offset -> one global atomicAdd per (block, offset).
// Per-thread hit list <= 8 entries (parity admits at most 8 candidate taps).
__global__ __launch_bounds__(512) void probe_kernel(
    const void*  __restrict__ guide,
    const float* __restrict__ bias,
    float*       __restrict__ out,
    int ng)
{
    __shared__ int scnt[27];
    __shared__ int sbase[27];

    int t = threadIdx.x;
    if (t < 27) scnt[t] = 0;
    __syncthreads();

    int g = blockIdx.x * blockDim.x + t;
    bool valid = g < ng;

    int ho[8], hix[8], hpos[8];
    int nh = 0;

    if (valid) {
        int qx, qy, qz;
        load_xyz(guide, g, qx, qy, qz);
        #pragma unroll
        for (int o = 0; o < 27; o++) {
            const int ox = o / 9 - 1, oy = (o / 3) % 3 - 1, oz = o % 3 - 1;
            int px = qx - ox, py = qy - oy, pz = qz - oz;
            if ((((px | py | pz) & 1) == 0) &
                ((unsigned)px < 256u) & ((unsigned)py < 256u) & ((unsigned)pz < 256u)) {
                int cell = (px >> 1) | ((py >> 1) << 7) | ((pz >> 1) << 14);
                int idx = g_grid[cell];
                if (idx >= 0) {
                    ho[nh]   = o;
                    hix[nh]  = idx;
                    hpos[nh] = atomicAdd(&scnt[o], 1);   // smem: cheap
                    nh++;
                }
            }
        }
    }
    __syncthreads();

    if (t < 27) {
        int c = scnt[t];
        sbase[t] = c ? atomicAdd(&g_cnt[t], c) : 0;      // 27 global atomics / block
    }
    __syncthreads();

    for (int h = 0; h < nh; h++) {
        int o = ho[h];
        g_pairs[o * CAP + sbase[o] + hpos[h]] = make_int2(g, hix[h]);
    }

    if (valid) {
        // Initialize output row: bias (hits accumulate on top) or exact zero.
        float4* orow = (float4*)(out + (long long)g * 32);
        if (nh) {
            const float4* b4 = (const float4*)bias;
            #pragma unroll
            for (int i = 0; i < 8; i++) orow[i] = b4[i];
        } else {
            float4 zf = make_float4(0.f, 0.f, 0.f, 0.f);
            #pragma unroll
            for (int i = 0; i < 8; i++) orow[i] = zf;
        }
    }
}

// One block: build compact (offset, tile) worklist (parallel fill).
__global__ __launch_bounds__(1024) void build_work() {
    __shared__ int base[28];
    int t = threadIdx.x;
    if (t == 0) {
        int s = 0;
        for (int i = 0; i < 27; i++) {
            base[i] = s;
            s += (g_cnt[i] + TILE - 1) / TILE;
        }
        base[27] = s;
        g_nwork = s;
    }
    __syncthreads();
    for (int o = 0; o < 27; o++) {
        int b = base[o], n = base[o + 1] - b;
        for (int i = t; i < n; i += 1024) g_work[b + i] = (o << 16) | i;
    }
}

// CTA = one (offset, 128-row) tile. W[o] in smem, warp computes 16 rows x 32 cols.
__global__ __launch_bounds__(256) void gemm_kernel(
    const float* __restrict__ feats,
    float*       __restrict__ out)
{
    __shared__ int2   pairs[TILE];
    __shared__ float4 Wsh[512];          // 8 KB: W[o] packed by k4
    __shared__ float4 Fsh[TILE * 16];    // 32 KB: features [row][k4]

    int t = threadIdx.x, lane = t & 31, w = t >> 5;
    int nwork = g_nwork;

    for (int widx = blockIdx.x; widx < nwork; widx += gridDim.x) {
        int wk = g_work[widx];
        int o = wk >> 16, tile = wk & 0xffff;
        int cnt = g_cnt[o];
        int m0 = tile << 7;
        int m = min(TILE, cnt - m0);

        if (t < TILE && t < m) pairs[t] = g_pairs[o * CAP + m0 + t];
        Wsh[t]       = g_Wq[o * 512 + t];
        Wsh[t + 256] = g_Wq[o * 512 + t + 256];
        __syncthreads();

        const float4* f4p = (const float4*)feats;
        for (int v = t; v < (m << 4); v += 256) {
            int row = v >> 4, k4 = v & 15;
            Fsh[v] = f4p[(long long)pairs[row].y * 16 + k4];
        }
        __syncthreads();

        int r0 = w << 4;
        unsigned long long acc[16];
        #pragma unroll
        for (int r = 0; r < 16; r++) acc[r] = 0ull;

        #pragma unroll
        for (int k4 = 0; k4 < 16; k4++) {
            float4 w4 = Wsh[k4 * 32 + lane];                 // conflict-free LDS.128
            unsigned long long wxy = pack2(w4.x, w4.y);
            unsigned long long wzw = pack2(w4.z, w4.w);
            #pragma unroll
            for (int r = 0; r < 16; r++) {
                float4 f4 = Fsh[((r0 + r) << 4) + k4];       // broadcast LDS.128
                fma2(acc[r], pack2(f4.x, f4.y), wxy);
                fma2(acc[r], pack2(f4.z, f4.w), wzw);
            }
        }

        #pragma unroll
        for (int r = 0; r < 16; r++) {
            if (r0 + r < m) {
                float a, b;
                unpack2(acc[r], a, b);
                atomicAdd(&out[(long long)pairs[r0 + r].x * 32 + lane], a + b);  // RED
            }
        }
        __syncthreads();
    }
}

extern "C" void kernel_launch(void* const* d_in, const int* in_sizes, int n_in,
                              void* d_out, int out_size) {
    // Identify inputs by element count (order-agnostic).
    const float* feats = nullptr;
    const float* W     = nullptr;
    const float* bias  = nullptr;
    const void*  ic    = nullptr;
    const void*  gc    = nullptr;
    int np = 200000, ng = 400000;
    for (int i = 0; i < n_in; i++) {
        switch (in_sizes[i]) {
            case 12800000: feats = (const float*)d_in[i]; break;            // [Np,64]
            case 55296:    W     = (const float*)d_in[i]; break;            // [27,64,32]
            case 32:       bias  = (const float*)d_in[i]; break;            // [32]
            case 800000:   ic    = d_in[i]; np = in_sizes[i] / 4; break;    // [Np,4]
            case 1600000:  gc    = d_in[i]; ng = in_sizes[i] / 4; break;    // [Ng,4]
            default: break;
        }
    }
    if (!feats) feats = (const float*)d_in[0];
    if (!W)     W     = (const float*)d_in[1];
    if (!bias)  bias  = (const float*)d_in[2];
    if (!ic)    ic    = d_in[3];
    if (!gc)    gc    = d_in[4];
    float* out = (float*)d_out;

    void* gptr = nullptr;
    cudaGetSymbolAddress(&gptr, g_grid);
    cudaMemsetAsync(gptr, 0xFF, sizeof(int) * (1 << 21), 0);
    void* cptr = nullptr;
    cudaGetSymbolAddress(&cptr, g_cnt);
    cudaMemsetAsync(cptr, 0, sizeof(int) * 27, 0);

    detect_dtype<<<1, 1>>>((const int*)gc);
    populate_grid<<<(np + 255) / 256, 256>>>(ic, np);
    pack_weights<<<(27 * 512 + 255) / 256, 256>>>(W);
    probe_kernel<<<(ng + 511) / 512, 512>>>(gc, bias, out, ng);
    build_work<<<1, 1024>>>();
    gemm_kernel<<<2048, 256>>>(feats, out);
}

// round 9
// speedup vs baseline: 2.0933x; 1.2515x over previous
#include <cuda_runtime.h>
#include <cuda_bf16.h>

// Sparse generative transpose conv (3x3x3, stride 2), pruned to guide coords.
// R8 (= R7 re-bench; prior round was an infra failure): offset-grouped
// gather-GEMM; scatter epilogue staged through smem and issued as
// red.global.add.v4.f32 (4x fewer REDG lanes than scalar atomics).

#define FULLMASK 0xffffffffu
#define CAP 400000           // max pairs per offset (<= Ng)
#define TILE 128

__device__ int    g_grid[1 << 21];        // 128^3 cells -> input index or -1
__device__ float4 g_Wq[27 * 512];         // Wq[o][k4][j] = W[o][4k4+0..3][j]
__device__ int    g_is64;                 // 1 if coords are int64
__device__ int    g_cnt[27];              // pairs per offset
__device__ int2   g_pairs[27 * CAP];      // (guide, input) pairs per offset
__device__ int    g_nwork;                // number of GEMM tiles
__device__ int    g_work[27 * ((CAP + TILE - 1) / TILE) + 32];

__device__ __forceinline__ unsigned long long pack2(float a, float b) {
    unsigned long long r;
    asm("mov.b64 %0, {%1, %2};" : "=l"(r) : "f"(a), "f"(b));
    return r;
}
__device__ __forceinline__ void unpack2(unsigned long long v, float& a, float& b) {
    asm("mov.b64 {%0, %1}, %2;" : "=f"(a), "=f"(b) : "l"(v));
}
__device__ __forceinline__ void fma2(unsigned long long& acc,
                                     unsigned long long a, unsigned long long b) {
    asm("fma.rn.f32x2 %0, %1, %2, %0;" : "+l"(acc) : "l"(a), "l"(b));
}
// out is a device-global allocation, so the generic address maps to global space.
__device__ __forceinline__ void red4(float* p, float4 v) {
    asm volatile("red.global.add.v4.f32 [%0], {%1, %2, %3, %4};"
                 :: "l"(p), "f"(v.x), "f"(v.y), "f"(v.z), "f"(v.w) : "memory");
}

// int64 layout: odd int32 words are sign-extension halves of coords >= -1 -> {0,-1}.
__global__ void detect_dtype(const int* __restrict__ gc) {
    int t = threadIdx.x;
    int bad = 0;
    for (int i = 1 + 2 * t; i < 2048; i += 64) {
        int v = gc[i];
        bad |= (v != 0) & (v != -1);
    }
    bad = __any_sync(FULLMASK, bad);
    if (t == 0) g_is64 = bad ? 0 : 1;
}

__device__ __forceinline__ void load_xyz(const void* p, long long row,
                                         int& x, int& y, int& z) {
    if (g_is64) {
        const long long* q = (const long long*)p + row * 4;
        x = (int)q[1]; y = (int)q[2]; z = (int)q[3];
    } else {
        const int* q = (const int*)p + row * 4;
        x = q[1]; y = q[2]; z = q[3];
    }
}

__global__ void populate_grid(const void* __restrict__ ic, int np) {
    int i = blockIdx.x * blockDim.x + threadIdx.x;
    if (i >= np) return;
    int x, y, z;
    load_xyz(ic, i, x, y, z);
    if (((unsigned)x < 256u) & ((unsigned)y < 256u) & ((unsigned)z < 256u) &
        (((x | y | z) & 1) == 0)) {
        int cell = (x >> 1) | ((y >> 1) << 7) | ((z >> 1) << 14);
        g_grid[cell] = i;
    }
}

__global__ void pack_weights(const float* __restrict__ W) {
    int t = blockIdx.x * blockDim.x + threadIdx.x;
    if (t >= 27 * 512) return;
    int j  = t & 31;
    int k4 = (t >> 5) & 15;
    int o  = t >> 9;
    const float* b = W + ((o * 64 + 4 * k4) * 32 + j);
    g_Wq[t] = make_float4(b[0], b[32], b[64], b[96]);
}

// Thread-per-guide probe, block-aggregated bucket counters.
__global__ __launch_bounds__(512) void probe_kernel(
    const void*  __restrict__ guide,
    const float* __restrict__ bias,
    float*       __restrict__ out,
    int ng)
{
    __shared__ int scnt[27];
    __shared__ int sbase[27];

    int t = threadIdx.x;
    if (t < 27) scnt[t] = 0;
    __syncthreads();

    int g = blockIdx.x * blockDim.x + t;
    bool valid = g < ng;

    int ho[8], hix[8], hpos[8];
    int nh = 0;

    if (valid) {
        int qx, qy, qz;
        load_xyz(guide, g, qx, qy, qz);
        #pragma unroll
        for (int o = 0; o < 27; o++) {
            const int ox = o / 9 - 1, oy = (o / 3) % 3 - 1, oz = o % 3 - 1;
            int px = qx - ox, py = qy - oy, pz = qz - oz;
            if ((((px | py | pz) & 1) == 0) &
                ((unsigned)px < 256u) & ((unsigned)py < 256u) & ((unsigned)pz < 256u)) {
                int cell = (px >> 1) | ((py >> 1) << 7) | ((pz >> 1) << 14);
                int idx = g_grid[cell];
                if (idx >= 0) {
                    ho[nh]   = o;
                    hix[nh]  = idx;
                    hpos[nh] = atomicAdd(&scnt[o], 1);   // smem
                    nh++;
                }
            }
        }
    }
    __syncthreads();

    if (t < 27) {
        int c = scnt[t];
        sbase[t] = c ? atomicAdd(&g_cnt[t], c) : 0;      // 27 global atomics / block
    }
    __syncthreads();

    for (int h = 0; h < nh; h++) {
        int o = ho[h];
        g_pairs[o * CAP + sbase[o] + hpos[h]] = make_int2(g, hix[h]);
    }

    if (valid) {
        float4* orow = (float4*)(out + (long long)g * 32);
        if (nh) {
            const float4* b4 = (const float4*)bias;
            #pragma unroll
            for (int i = 0; i < 8; i++) orow[i] = b4[i];
        } else {
            float4 zf = make_float4(0.f, 0.f, 0.f, 0.f);
            #pragma unroll
            for (int i = 0; i < 8; i++) orow[i] = zf;
        }
    }
}

// One block: build compact (offset, tile) worklist.
__global__ __launch_bounds__(1024) void build_work() {
    __shared__ int base[28];
    int t = threadIdx.x;
    if (t == 0) {
        int s = 0;
        for (int i = 0; i < 27; i++) {
            base[i] = s;
            s += (g_cnt[i] + TILE - 1) / TILE;
        }
        base[27] = s;
        g_nwork = s;
    }
    __syncthreads();
    for (int o = 0; o < 27; o++) {
        int b = base[o], n = base[o + 1] - b;
        for (int i = t; i < n; i += 1024) g_work[b + i] = (o << 16) | i;
    }
}

// CTA = one (offset, 128-row) tile. W[o] in smem, warp computes 16 rows x 32 cols.
// Epilogue: stage results in smem (aliasing Fsh), scatter via red.global.add.v4.f32.
__global__ __launch_bounds__(256) void gemm_kernel(
    const float* __restrict__ feats,
    float*       __restrict__ out)
{
    __shared__ int2   pairs[TILE];
    __shared__ float4 Wsh[512];          // 8 KB: W[o] packed by k4
    __shared__ float4 Fsh[TILE * 16];    // 32 KB: features [row][k4]; reused as stage

    float* stage = reinterpret_cast<float*>(Fsh);  // 128*32 floats = 16 KB

    int t = threadIdx.x, lane = t & 31, w = t >> 5;
    int nwork = g_nwork;

    for (int widx = blockIdx.x; widx < nwork; widx += gridDim.x) {
        int wk = g_work[widx];
        int o = wk >> 16, tile = wk & 0xffff;
        int cnt = g_cnt[o];
        int m0 = tile << 7;
        int m = min(TILE, cnt - m0);

        if (t < TILE && t < m) pairs[t] = g_pairs[o * CAP + m0 + t];
        Wsh[t]       = g_Wq[o * 512 + t];
        Wsh[t + 256] = g_Wq[o * 512 + t + 256];
        __syncthreads();

        const float4* f4p = (const float4*)feats;
        for (int v = t; v < (m << 4); v += 256) {
            int row = v >> 4, k4 = v & 15;
            Fsh[v] = f4p[(long long)pairs[row].y * 16 + k4];
        }
        __syncthreads();

        int r0 = w << 4;
        unsigned long long acc[16];
        #pragma unroll
        for (int r = 0; r < 16; r++) acc[r] = 0ull;

        #pragma unroll
        for (int k4 = 0; k4 < 16; k4++) {
            float4 w4 = Wsh[k4 * 32 + lane];                 // conflict-free LDS.128
            unsigned long long wxy = pack2(w4.x, w4.y);
            unsigned long long wzw = pack2(w4.z, w4.w);
            #pragma unroll
            for (int r = 0; r < 16; r++) {
                float4 f4 = Fsh[((r0 + r) << 4) + k4];       // broadcast LDS.128
                fma2(acc[r], pack2(f4.x, f4.y), wxy);
                fma2(acc[r], pack2(f4.z, f4.w), wzw);
            }
        }
        __syncthreads();   // all warps done reading Fsh

        #pragma unroll
        for (int r = 0; r < 16; r++) {
            float a, b;
            unpack2(acc[r], a, b);
            stage[((r0 + r) << 5) + lane] = a + b;           // conflict-free STS
        }
        __syncthreads();

        // Vector scatter: 8 float4 per row; m*8 vector atomics per tile.
        for (int v = t; v < (m << 3); v += 256) {
            int row = v >> 3, c4 = v & 7;
            float4 val = reinterpret_cast<float4*>(stage)[(row << 3) + c4];
            red4(out + (long long)pairs[row].x * 32 + (c4 << 2), val);
        }
        __syncthreads();
    }
}

extern "C" void kernel_launch(void* const* d_in, const int* in_sizes, int n_in,
                              void* d_out, int out_size) {
    // Identify inputs by element count (order-agnostic).
    const float* feats = nullptr;
    const float* W     = nullptr;
    const float* bias  = nullptr;
    const void*  ic    = nullptr;
    const void*  gc    = nullptr;
    int np = 200000, ng = 400000;
    for (int i = 0; i < n_in; i++) {
        switch (in_sizes[i]) {
            case 12800000: feats = (const float*)d_in[i]; break;            // [Np,64]
            case 55296:    W     = (const float*)d_in[i]; break;            // [27,64,32]
            case 32:       bias  = (const float*)d_in[i]; break;            // [32]
            case 800000:   ic    = d_in[i]; np = in_sizes[i] / 4; break;    // [Np,4]
            case 1600000:  gc    = d_in[i]; ng = in_sizes[i] / 4; break;    // [Ng,4]
            default: break;
        }
    }
    if (!feats) feats = (const float*)d_in[0];
    if (!W)     W     = (const float*)d_in[1];
    if (!bias)  bias  = (const float*)d_in[2];
    if (!ic)    ic    = d_in[3];
    if (!gc)    gc    = d_in[4];
    float* out = (float*)d_out;

    void* gptr = nullptr;
    cudaGetSymbolAddress(&gptr, g_grid);
    cudaMemsetAsync(gptr, 0xFF, sizeof(int) * (1 << 21), 0);
    void* cptr = nullptr;
    cudaGetSymbolAddress(&cptr, g_cnt);
    cudaMemsetAsync(cptr, 0, sizeof(int) * 27, 0);

    detect_dtype<<<1, 32>>>((const int*)gc);
    populate_grid<<<(np + 255) / 256, 256>>>(ic, np);
    pack_weights<<<(27 * 512 + 255) / 256, 256>>>(W);
    probe_kernel<<<(ng + 511) / 512, 512>>>(gc, bias, out, ng);
    build_work<<<1, 1024>>>();
    gemm_kernel<<<2048, 256>>>(feats, out);
}